// round 1
// baseline (speedup 1.0000x reference)
#include <cuda_runtime.h>

#define N_NODES 100000
#define D       128
#define R       4
#define E       500000

// ---------------- scratch (static device globals; no runtime allocs) ----------
__device__ float g_acc[(size_t)R * N_NODES * D];   // per-relation neighbor sums (204.8 MB)
__device__ float g_cnt[R * N_NODES];               // per-relation in-degree
__device__ float g_Wc[(R + 1) * D * D];            // [W̄self ; Wn_0/4 ; ... ; Wn_3/4]
__device__ float g_bavg[D];                        // mean bias

// ---------------- zero accumulators -------------------------------------------
__global__ __launch_bounds__(256) void zero_kernel() {
    size_t i = (size_t)blockIdx.x * blockDim.x + threadIdx.x;   // 50000*256 = 12.8M
    ((float4*)g_acc)[i] = make_float4(0.f, 0.f, 0.f, 0.f);
    if (i < (size_t)R * N_NODES) g_cnt[i] = 0.f;
}

// ---------------- precombine weights (mean over relations) --------------------
__global__ __launch_bounds__(256) void combine_kernel(const float* __restrict__ Ws,
                                                      const float* __restrict__ Wn,
                                                      const float* __restrict__ b) {
    int i = blockIdx.x * blockDim.x + threadIdx.x;
    if (i < D * D) {
        float s = 0.f;
        #pragma unroll
        for (int r = 0; r < R; r++) s += Ws[r * D * D + i];
        g_Wc[i] = s * 0.25f;
        #pragma unroll
        for (int r = 0; r < R; r++) g_Wc[(1 + r) * D * D + i] = Wn[r * D * D + i] * 0.25f;
    }
    if (i < D) {
        float s = 0.f;
        #pragma unroll
        for (int r = 0; r < R; r++) s += b[r * D + i];
        g_bavg[i] = s * 0.25f;
    }
}

// ---------------- edge scatter: one warp per edge ------------------------------
__global__ __launch_bounds__(256) void scatter_kernel(const float* __restrict__ x,
                                                      const int*   __restrict__ src,
                                                      const int*   __restrict__ dst) {
    int wg   = (int)(((size_t)blockIdx.x * blockDim.x + threadIdx.x) >> 5);
    int lane = threadIdx.x & 31;
    if (wg >= R * E) return;
    int r = wg / E;
    int s = src[wg];
    int d = dst[wg];

    float4 v = *(const float4*)(x + (size_t)s * D + lane * 4);
    float* o = g_acc + ((size_t)r * N_NODES + d) * D + lane * 4;
    atomicAdd(o + 0, v.x);
    atomicAdd(o + 1, v.y);
    atomicAdd(o + 2, v.z);
    atomicAdd(o + 3, v.w);
    if (lane == 0) atomicAdd(&g_cnt[r * N_NODES + d], 1.0f);
}

// ---------------- fused GEMM: out = [x | neigh_0..3] @ g_Wc + b̄ ----------------
// Virtual K = 5*128. M-tile 64, full 128 output cols, K-tile 32.
// 256 threads as 16x16; each thread computes 4 rows x 8 cols.
#define MT 64
#define KT 32

__global__ __launch_bounds__(256) void gemm_kernel(const float* __restrict__ x,
                                                   float* __restrict__ out) {
    __shared__ float As[KT][68];        // transposed A tile (padded, 16B-aligned rows)
    __shared__ float Bs[KT][128];
    __shared__ float invc_s[R][MT];

    int tid  = threadIdx.x;
    int ty   = tid >> 4;                // 0..15
    int tx   = tid & 15;                // 0..15
    int row0 = blockIdx.x * MT;

    if (tid < R * MT) {
        int r = tid / MT, rr = tid % MT;
        int n = row0 + rr;
        float c = (n < N_NODES) ? g_cnt[r * N_NODES + n] : 1.f;
        invc_s[r][rr] = 1.f / fmaxf(c, 1.f);
    }

    float acc[4][8];
    #pragma unroll
    for (int i = 0; i < 4; i++)
        #pragma unroll
        for (int j = 0; j < 8; j++) acc[i][j] = 0.f;

    for (int seg = 0; seg < R + 1; seg++) {
        const float* Asrc = (seg == 0) ? x : (g_acc + (size_t)(seg - 1) * N_NODES * D);
        const float* Bsrc = g_Wc + seg * D * D;

        for (int k0 = 0; k0 < D; k0 += KT) {
            __syncthreads();
            // A tile: 64 rows x 32 k, stored transposed, scaled by 1/cnt for neigh segs
            {
                int f4 = tid & 7;           // which float4 along k
                int rb = tid >> 3;          // 0..31
                #pragma unroll
                for (int p = 0; p < 2; p++) {
                    int rr = rb + p * 32;
                    int n  = row0 + rr;
                    float4 v = make_float4(0.f, 0.f, 0.f, 0.f);
                    if (n < N_NODES)
                        v = *(const float4*)(Asrc + (size_t)n * D + k0 + f4 * 4);
                    float sc = (seg == 0) ? 1.f : invc_s[seg - 1][rr];
                    As[f4 * 4 + 0][rr] = v.x * sc;
                    As[f4 * 4 + 1][rr] = v.y * sc;
                    As[f4 * 4 + 2][rr] = v.z * sc;
                    As[f4 * 4 + 3][rr] = v.w * sc;
                }
            }
            // B tile: 32 k-rows x 128 cols
            {
                int c4 = tid & 31;
                int rb = tid >> 5;          // 0..7
                #pragma unroll
                for (int p = 0; p < 4; p++) {
                    int kk = rb + p * 8;
                    *(float4*)&Bs[kk][c4 * 4] =
                        *(const float4*)(Bsrc + (size_t)(k0 + kk) * D + c4 * 4);
                }
            }
            __syncthreads();
            #pragma unroll
            for (int kk = 0; kk < KT; kk++) {
                float4 a  = *(const float4*)&As[kk][ty * 4];
                float4 b0 = *(const float4*)&Bs[kk][tx * 8];
                float4 b1 = *(const float4*)&Bs[kk][tx * 8 + 4];
                float av[4] = {a.x, a.y, a.z, a.w};
                float bv[8] = {b0.x, b0.y, b0.z, b0.w, b1.x, b1.y, b1.z, b1.w};
                #pragma unroll
                for (int i = 0; i < 4; i++)
                    #pragma unroll
                    for (int j = 0; j < 8; j++)
                        acc[i][j] += av[i] * bv[j];
            }
        }
    }

    // epilogue: add mean bias, store
    #pragma unroll
    for (int i = 0; i < 4; i++) {
        int n = row0 + ty * 4 + i;
        if (n < N_NODES) {
            #pragma unroll
            for (int j = 0; j < 8; j += 4) {
                float4 o;
                o.x = acc[i][j + 0] + g_bavg[tx * 8 + j + 0];
                o.y = acc[i][j + 1] + g_bavg[tx * 8 + j + 1];
                o.z = acc[i][j + 2] + g_bavg[tx * 8 + j + 2];
                o.w = acc[i][j + 3] + g_bavg[tx * 8 + j + 3];
                *(float4*)(out + (size_t)n * D + tx * 8 + j) = o;
            }
        }
    }
}

// ---------------- launch --------------------------------------------------------
extern "C" void kernel_launch(void* const* d_in, const int* in_sizes, int n_in,
                              void* d_out, int out_size) {
    const float* x      = (const float*)d_in[0];
    const int*   src    = (const int*)d_in[1];
    const int*   dst    = (const int*)d_in[2];
    const float* Wself  = (const float*)d_in[3];
    const float* Wneigh = (const float*)d_in[4];
    const float* b      = (const float*)d_in[5];
    float* out = (float*)d_out;

    zero_kernel<<<50000, 256>>>();                       // 12.8M float4
    combine_kernel<<<(D * D + 255) / 256, 256>>>(Wself, Wneigh, b);
    scatter_kernel<<<(R * E * 32 + 255) / 256, 256>>>(x, src, dst);  // 1 warp/edge
    gemm_kernel<<<(N_NODES + MT - 1) / MT, 256>>>(x, out);
    (void)in_sizes; (void)n_in; (void)out_size;
}

// round 2
// speedup vs baseline: 1.9575x; 1.9575x over previous
#include <cuda_runtime.h>

#define N_NODES 100000
#define D       128
#define R       4
#define E       500000

// ---------------- scratch (static device globals; no runtime allocs) ----------
__device__ float g_acc[(size_t)R * N_NODES * D];   // per-relation neighbor sums (204.8 MB)
__device__ float g_cnt[R * N_NODES];               // per-relation in-degree
__device__ float g_Wc[(R + 1) * D * D];            // [W̄self ; Wn_0/4 ; ... ; Wn_3/4]
__device__ float g_bavg[D];                        // mean bias

// ---------------- zero accumulators -------------------------------------------
__global__ __launch_bounds__(256) void zero_kernel() {
    size_t i = (size_t)blockIdx.x * blockDim.x + threadIdx.x;   // 50000*256 = 12.8M
    ((float4*)g_acc)[i] = make_float4(0.f, 0.f, 0.f, 0.f);
    if (i < (size_t)R * N_NODES) g_cnt[i] = 0.f;
}

// ---------------- precombine weights (mean over relations) --------------------
__global__ __launch_bounds__(256) void combine_kernel(const float* __restrict__ Ws,
                                                      const float* __restrict__ Wn,
                                                      const float* __restrict__ b) {
    int i = blockIdx.x * blockDim.x + threadIdx.x;
    if (i < D * D) {
        float s = 0.f;
        #pragma unroll
        for (int r = 0; r < R; r++) s += Ws[r * D * D + i];
        g_Wc[i] = s * 0.25f;
        #pragma unroll
        for (int r = 0; r < R; r++) g_Wc[(1 + r) * D * D + i] = Wn[r * D * D + i] * 0.25f;
    }
    if (i < D) {
        float s = 0.f;
        #pragma unroll
        for (int r = 0; r < R; r++) s += b[r * D + i];
        g_bavg[i] = s * 0.25f;
    }
}

// ---------------- edge scatter: one warp per edge, vector reds ------------------
__device__ __forceinline__ void red_add_v4(float* p, float4 v) {
    asm volatile("red.global.add.v4.f32 [%0], {%1,%2,%3,%4};"
                 :: "l"(p), "f"(v.x), "f"(v.y), "f"(v.z), "f"(v.w) : "memory");
}
__device__ __forceinline__ void red_add_f32(float* p, float v) {
    asm volatile("red.global.add.f32 [%0], %1;" :: "l"(p), "f"(v) : "memory");
}

__global__ __launch_bounds__(256) void scatter_kernel(const float* __restrict__ x,
                                                      const int*   __restrict__ src,
                                                      const int*   __restrict__ dst) {
    int wg   = (int)(((size_t)blockIdx.x * blockDim.x + threadIdx.x) >> 5);
    int lane = threadIdx.x & 31;
    if (wg >= R * E) return;
    int r = wg / E;
    int s = src[wg];
    int d = dst[wg];

    float4 v = *(const float4*)(x + (size_t)s * D + lane * 4);
    float* o = g_acc + ((size_t)r * N_NODES + d) * D + lane * 4;
    red_add_v4(o, v);
    if (lane == 0) red_add_f32(&g_cnt[r * N_NODES + d], 1.0f);
}

// ---------------- fused GEMM: out = [x | neigh_0..3] @ g_Wc + b̄ ----------------
// Virtual K = 5*128. Tile: 128 rows x 128 cols, KT=32, 128 threads.
// Thread grid 16x8: each thread computes 8 rows x 16 cols (asymmetric tile so
// LDS traffic (96B per 128 FMA) stays under the 128B/cyc smem crossbar).
#define MT 128
#define KT 32

__global__ __launch_bounds__(128) void gemm_kernel(const float* __restrict__ x,
                                                   float* __restrict__ out) {
    __shared__ float As[KT][MT + 8];     // transposed A tile; stride 136 (16B-aligned)
    __shared__ float Bs[KT][128];
    __shared__ float invc_s[R][MT];

    int tid = threadIdx.x;
    int rg  = tid >> 3;                  // 0..15 : row group (8 rows)
    int cg  = tid & 7;                   // 0..7  : col group (16 cols)
    int row0 = blockIdx.x * MT;

    // per-row 1/max(cnt,1) for each relation
    #pragma unroll
    for (int p = 0; p < 4; p++) {
        int i = tid + p * 128;           // covers R*MT = 512
        int r = i >> 7, rr = i & 127;
        int n = row0 + rr;
        float c = (n < N_NODES) ? g_cnt[r * N_NODES + n] : 1.f;
        invc_s[r][rr] = 1.f / fmaxf(c, 1.f);
    }

    float acc[8][16];
    #pragma unroll
    for (int i = 0; i < 8; i++)
        #pragma unroll
        for (int j = 0; j < 16; j++) acc[i][j] = 0.f;

    #pragma unroll 1
    for (int seg = 0; seg < R + 1; seg++) {
        const float* Asrc = (seg == 0) ? x : (g_acc + (size_t)(seg - 1) * N_NODES * D);
        const float* Bsrc = g_Wc + seg * D * D;

        #pragma unroll 1
        for (int k0 = 0; k0 < D; k0 += KT) {
            __syncthreads();
            // A tile: one row per thread, 32 k-values, stored transposed, pre-scaled
            {
                int n = row0 + tid;
                float sc = (seg == 0) ? 1.f : invc_s[seg - 1][tid];
                if (n < N_NODES) {
                    const float* ap = Asrc + (size_t)n * D + k0;
                    #pragma unroll
                    for (int f = 0; f < 8; f++) {
                        float4 v = *(const float4*)(ap + f * 4);
                        As[f * 4 + 0][tid] = v.x * sc;
                        As[f * 4 + 1][tid] = v.y * sc;
                        As[f * 4 + 2][tid] = v.z * sc;
                        As[f * 4 + 3][tid] = v.w * sc;
                    }
                } else {
                    #pragma unroll
                    for (int f = 0; f < KT; f++) As[f][tid] = 0.f;
                }
            }
            // B tile: 32 k-rows x 128 cols, coalesced float4
            {
                #pragma unroll
                for (int p = 0; p < 8; p++) {
                    int f4 = tid + p * 128;          // 0..1023
                    int kk = f4 >> 5;
                    int c4 = f4 & 31;
                    *(float4*)&Bs[kk][c4 * 4] =
                        *(const float4*)(Bsrc + (size_t)(k0 + kk) * D + c4 * 4);
                }
            }
            __syncthreads();
            #pragma unroll
            for (int kk = 0; kk < KT; kk++) {
                float a[8], b[16];
                *(float4*)&a[0] = *(const float4*)&As[kk][rg * 8];
                *(float4*)&a[4] = *(const float4*)&As[kk][rg * 8 + 4];
                #pragma unroll
                for (int q = 0; q < 4; q++)
                    *(float4*)&b[q * 4] = *(const float4*)&Bs[kk][cg * 16 + q * 4];
                #pragma unroll
                for (int i = 0; i < 8; i++)
                    #pragma unroll
                    for (int j = 0; j < 16; j++)
                        acc[i][j] += a[i] * b[j];
            }
        }
    }

    // epilogue: add mean bias, store
    #pragma unroll
    for (int i = 0; i < 8; i++) {
        int n = row0 + rg * 8 + i;
        if (n < N_NODES) {
            #pragma unroll
            for (int j = 0; j < 16; j += 4) {
                float4 o;
                o.x = acc[i][j + 0] + g_bavg[cg * 16 + j + 0];
                o.y = acc[i][j + 1] + g_bavg[cg * 16 + j + 1];
                o.z = acc[i][j + 2] + g_bavg[cg * 16 + j + 2];
                o.w = acc[i][j + 3] + g_bavg[cg * 16 + j + 3];
                *(float4*)(out + (size_t)n * D + cg * 16 + j) = o;
            }
        }
    }
}

// ---------------- launch --------------------------------------------------------
extern "C" void kernel_launch(void* const* d_in, const int* in_sizes, int n_in,
                              void* d_out, int out_size) {
    const float* x      = (const float*)d_in[0];
    const int*   src    = (const int*)d_in[1];
    const int*   dst    = (const int*)d_in[2];
    const float* Wself  = (const float*)d_in[3];
    const float* Wneigh = (const float*)d_in[4];
    const float* b      = (const float*)d_in[5];
    float* out = (float*)d_out;

    zero_kernel<<<50000, 256>>>();
    combine_kernel<<<(D * D + 255) / 256, 256>>>(Wself, Wneigh, b);
    scatter_kernel<<<(R * E * 32 + 255) / 256, 256>>>(x, src, dst);  // 1 warp/edge
    gemm_kernel<<<(N_NODES + MT - 1) / MT, 256 / 2>>>(x, out);
    (void)in_sizes; (void)n_in; (void)out_size;
}

// round 4
// speedup vs baseline: 6.1440x; 3.1387x over previous
#include <cuda_runtime.h>
#include <cstdint>

#define N_NODES 100000
#define D       128
#define R       4
#define E       500000
#define RN      (R * N_NODES)   // 400000
#define REDGES  (R * E)         // 2000000
#define NB      782             // scan blocks (512 elems each) : 782*512 >= 400000
#define NTILE   782             // ceil(N_NODES/128)

// ---------------- scratch (static device globals; no runtime allocs) ----------
__device__ float g_neigh[(size_t)R * N_NODES * D];   // mean-aggregated neighbors (204.8 MB)
__device__ int   g_cnti[RN];
__device__ int   g_fill[RN];
__device__ int   g_off[RN];
__device__ int   g_bsum[1024];
__device__ int   g_bscan[1024];
__device__ int   g_esrc[REDGES];                     // CSR-bucketed source ids
__device__ float g_Wt[(R + 1) * D * D];              // [seg][k][n], scaled
__device__ float g_bavg[D];

// =================== helpers ====================================================
__device__ __forceinline__ uint32_t f2tf32(float f) {
    uint32_t u;
    asm("cvt.rna.tf32.f32 %0, %1;" : "=r"(u) : "f"(f));
    return u;
}
__device__ __forceinline__ void mma8(float* c, const uint32_t* a, const uint32_t* b) {
    asm volatile(
        "mma.sync.aligned.m16n8k8.row.col.f32.tf32.tf32.f32 "
        "{%0,%1,%2,%3}, {%4,%5,%6,%7}, {%8,%9}, {%0,%1,%2,%3};"
        : "+f"(c[0]), "+f"(c[1]), "+f"(c[2]), "+f"(c[3])
        : "r"(a[0]), "r"(a[1]), "r"(a[2]), "r"(a[3]), "r"(b[0]), "r"(b[1]));
}

// ---------------- weight precombine: g_Wt[seg][k][n] ---------------------------
__global__ __launch_bounds__(256) void combine_kernel(const float* __restrict__ Ws,
                                                      const float* __restrict__ Wn,
                                                      const float* __restrict__ b) {
    int i = blockIdx.x * blockDim.x + threadIdx.x;
    if (i < (R + 1) * D * D) {
        int seg = i >> 14, rem = i & 16383;
        float v;
        if (seg == 0) {
            v = 0.f;
            #pragma unroll
            for (int r = 0; r < R; r++) v += Ws[r * D * D + rem];
            v *= 0.25f;
        } else {
            v = Wn[(seg - 1) * D * D + rem] * 0.25f;
        }
        g_Wt[i] = v;
    }
    if (i < D) {
        float s = 0.f;
        #pragma unroll
        for (int r = 0; r < R; r++) s += b[r * D + i];
        g_bavg[i] = s * 0.25f;
    }
}

// ---------------- CSR build ----------------------------------------------------
__global__ __launch_bounds__(256) void zero_kernel() {
    int i = blockIdx.x * blockDim.x + threadIdx.x;
    if (i < RN) { g_cnti[i] = 0; g_fill[i] = 0; }
}
__global__ __launch_bounds__(256) void count_kernel(const int* __restrict__ dst) {
    int i = blockIdx.x * blockDim.x + threadIdx.x;
    if (i >= REDGES) return;
    int r = i / E;
    atomicAdd(&g_cnti[r * N_NODES + dst[i]], 1);
}
__global__ __launch_bounds__(512) void scan1_kernel() {
    __shared__ int tmp[512];
    int t = threadIdx.x, i = blockIdx.x * 512 + t;
    int v = (i < RN) ? g_cnti[i] : 0;
    tmp[t] = v;
    __syncthreads();
    for (int o = 1; o < 512; o <<= 1) {
        int a = (t >= o) ? tmp[t - o] : 0;
        __syncthreads();
        tmp[t] += a;
        __syncthreads();
    }
    if (i < RN) g_off[i] = tmp[t] - v;
    if (t == 511) g_bsum[blockIdx.x] = tmp[511];
}
__global__ __launch_bounds__(1024) void scan2_kernel() {
    __shared__ int tmp[1024];
    int t = threadIdx.x;
    int v = (t < NB) ? g_bsum[t] : 0;
    tmp[t] = v;
    __syncthreads();
    for (int o = 1; o < 1024; o <<= 1) {
        int a = (t >= o) ? tmp[t - o] : 0;
        __syncthreads();
        tmp[t] += a;
        __syncthreads();
    }
    if (t < NB) g_bscan[t] = tmp[t] - v;
}
__global__ __launch_bounds__(512) void scan3_kernel() {
    int i = blockIdx.x * 512 + threadIdx.x;
    if (i < RN) g_off[i] += g_bscan[blockIdx.x];
}
__global__ __launch_bounds__(256) void fill_kernel(const int* __restrict__ src,
                                                   const int* __restrict__ dst) {
    int i = blockIdx.x * blockDim.x + threadIdx.x;
    if (i >= REDGES) return;
    int r = i / E;
    int rd = r * N_NODES + dst[i];
    int pos = g_off[rd] + atomicAdd(&g_fill[rd], 1);
    g_esrc[pos] = src[i];
}

// ---------------- aggregate: warp per node, gathers from L2-resident x ---------
__global__ __launch_bounds__(256) void aggregate_kernel(const float* __restrict__ x) {
    int w = (int)(((size_t)blockIdx.x * blockDim.x + threadIdx.x) >> 5);
    int lane = threadIdx.x & 31;
    if (w >= N_NODES) return;

    #pragma unroll
    for (int r = 0; r < R; r++) {
        int rd = r * N_NODES + w;
        int base = g_off[rd];
        int c = g_cnti[rd];
        float4 s0 = make_float4(0.f, 0.f, 0.f, 0.f);
        float4 s1 = make_float4(0.f, 0.f, 0.f, 0.f);
        int e = 0;
        for (; e + 2 <= c; e += 2) {
            int sa = g_esrc[base + e];
            int sb = g_esrc[base + e + 1];
            float4 va = *(const float4*)(x + (size_t)sa * D + lane * 4);
            float4 vb = *(const float4*)(x + (size_t)sb * D + lane * 4);
            s0.x += va.x; s0.y += va.y; s0.z += va.z; s0.w += va.w;
            s1.x += vb.x; s1.y += vb.y; s1.z += vb.z; s1.w += vb.w;
        }
        if (e < c) {
            int sa = g_esrc[base + e];
            float4 va = *(const float4*)(x + (size_t)sa * D + lane * 4);
            s0.x += va.x; s0.y += va.y; s0.z += va.z; s0.w += va.w;
        }
        float ic = 1.f / fmaxf((float)c, 1.f);
        float4 o;
        o.x = (s0.x + s1.x) * ic;
        o.y = (s0.y + s1.y) * ic;
        o.z = (s0.z + s1.z) * ic;
        o.w = (s0.w + s1.w) * ic;
        *(float4*)(g_neigh + (size_t)rd * D + lane * 4) = o;
    }
}

// ---------------- tf32 mma.sync GEMM: out = Σ_seg A_seg @ B_seg + b̄ -----------
// Block tile 128x128, 128 threads = 4 warps in 2x2, warp tile 64x64.
// A chunk stored transposed [k][m] (stride 136) with XOR swizzle on m by
// ((k>>2)&3)<<3 so both stores (2-way) and fragment loads (conflict-free) work.
__global__ __launch_bounds__(128) void gemm_kernel(const float* __restrict__ x,
                                                   float* __restrict__ out) {
    __shared__ uint32_t As[32][136];
    __shared__ uint32_t Bs[32][136];

    int tid  = threadIdx.x;
    int wid  = tid >> 5, lane = tid & 31;
    int qid  = lane >> 2, kid = lane & 3;
    int wm   = wid & 1, wn = wid >> 1;
    int row0 = blockIdx.x * 128;

    float c[4][8][4];
    #pragma unroll
    for (int mt = 0; mt < 4; mt++)
        #pragma unroll
        for (int nt = 0; nt < 8; nt++)
            #pragma unroll
            for (int j = 0; j < 4; j++) c[mt][nt][j] = 0.f;

    #pragma unroll 1
    for (int seg = 0; seg < R + 1; seg++) {
        const float* Asrc = (seg == 0) ? x : (g_neigh + (size_t)(seg - 1) * N_NODES * D);
        const float* Bsrc = g_Wt + seg * D * D;

        #pragma unroll 1
        for (int k0 = 0; k0 < D; k0 += 32) {
            __syncthreads();
            // ---- A chunk: 128 rows x 32 k -> transposed+swizzled ----
            #pragma unroll
            for (int p = 0; p < 8; p++) {
                int q = tid + p * 128;          // 0..1023
                int row = q >> 3, kq = q & 7;
                int n = row0 + row;
                float4 v = make_float4(0.f, 0.f, 0.f, 0.f);
                if (n < N_NODES) v = *(const float4*)(Asrc + (size_t)n * D + k0 + kq * 4);
                #pragma unroll
                for (int i = 0; i < 4; i++) {
                    int k = kq * 4 + i;
                    float f = (i == 0) ? v.x : (i == 1) ? v.y : (i == 2) ? v.z : v.w;
                    As[k][row ^ (((k >> 2) & 3) << 3)] = f2tf32(f);
                }
            }
            // ---- B chunk: 32 k-rows x 128 n, natural layout ----
            #pragma unroll
            for (int p = 0; p < 8; p++) {
                int q = tid + p * 128;
                int kk = q >> 5, nq = q & 31;
                float4 v = *(const float4*)(Bsrc + (size_t)(k0 + kk) * D + nq * 4);
                uint4 u;
                u.x = f2tf32(v.x); u.y = f2tf32(v.y); u.z = f2tf32(v.z); u.w = f2tf32(v.w);
                *(uint4*)&Bs[kk][nq * 4] = u;
            }
            __syncthreads();
            // ---- 4 k8-steps ----
            #pragma unroll
            for (int kk8 = 0; kk8 < 4; kk8++) {
                int k8 = kk8 * 8;
                int C0 = ((2 * kk8) & 3) << 3;
                int C1 = ((2 * kk8 + 1) & 3) << 3;
                uint32_t a[4][4], b[8][2];
                #pragma unroll
                for (int mt = 0; mt < 4; mt++) {
                    int row = wm * 64 + mt * 16 + qid;
                    a[mt][0] = As[k8 + kid][row ^ C0];
                    a[mt][1] = As[k8 + kid][(row + 8) ^ C0];
                    a[mt][2] = As[k8 + 4 + kid][row ^ C1];
                    a[mt][3] = As[k8 + 4 + kid][(row + 8) ^ C1];
                }
                #pragma unroll
                for (int nt = 0; nt < 8; nt++) {
                    int col = wn * 64 + nt * 8 + qid;
                    b[nt][0] = Bs[k8 + kid][col];
                    b[nt][1] = Bs[k8 + 4 + kid][col];
                }
                #pragma unroll
                for (int mt = 0; mt < 4; mt++)
                    #pragma unroll
                    for (int nt = 0; nt < 8; nt++)
                        mma8(c[mt][nt], a[mt], b[nt]);
            }
        }
    }

    // ---- epilogue: add mean bias, store float2 pairs ----
    #pragma unroll
    for (int mt = 0; mt < 4; mt++) {
        int r0q = row0 + wm * 64 + mt * 16 + qid;
        #pragma unroll
        for (int nt = 0; nt < 8; nt++) {
            int col = wn * 64 + nt * 8 + kid * 2;
            float b0 = g_bavg[col], b1 = g_bavg[col + 1];
            if (r0q < N_NODES) {
                float2 o = make_float2(c[mt][nt][0] + b0, c[mt][nt][1] + b1);
                *(float2*)(out + (size_t)r0q * D + col) = o;
            }
            if (r0q + 8 < N_NODES) {
                float2 o = make_float2(c[mt][nt][2] + b0, c[mt][nt][3] + b1);
                *(float2*)(out + (size_t)(r0q + 8) * D + col) = o;
            }
        }
    }
}

// ---------------- launch --------------------------------------------------------
extern "C" void kernel_launch(void* const* d_in, const int* in_sizes, int n_in,
                              void* d_out, int out_size) {
    const float* x      = (const float*)d_in[0];
    const int*   src    = (const int*)d_in[1];
    const int*   dst    = (const int*)d_in[2];
    const float* Wself  = (const float*)d_in[3];
    const float* Wneigh = (const float*)d_in[4];
    const float* b      = (const float*)d_in[5];
    float* out = (float*)d_out;

    combine_kernel<<<((R + 1) * D * D + 255) / 256, 256>>>(Wself, Wneigh, b);
    zero_kernel<<<(RN + 255) / 256, 256>>>();
    count_kernel<<<(REDGES + 255) / 256, 256>>>(dst);
    scan1_kernel<<<NB, 512>>>();
    scan2_kernel<<<1, 1024>>>();
    scan3_kernel<<<NB, 512>>>();
    fill_kernel<<<(REDGES + 255) / 256, 256>>>(src, dst);
    aggregate_kernel<<<(N_NODES * 32 + 255) / 256, 256>>>(x);
    gemm_kernel<<<NTILE, 128>>>(x, out);
    (void)in_sizes; (void)n_in; (void)out_size;
}